// round 6
// baseline (speedup 1.0000x reference)
#include <cuda_runtime.h>

// Problem constants (fixed by the reference)
constexpr int NB   = 32;   // neighbors per query
constexpr int A    = 4;    // anchors
constexpr int K    = 15;   // kernel points
constexpr int CIN  = 32;
constexpr int COUT = 32;
constexpr int NQ   = 16000;
constexpr int ROWS_TOT = NQ * A;          // 64000 (n,a) rows
constexpr int KC   = K * CIN;             // 480 reduction length
constexpr int QB   = 8;                   // queries per block (kernel A)
constexpr int RB   = 32;                  // rows per block (kernel B)
constexpr int WF_PAD = KC + 4;            // 484 floats: stride 121 float4, 121 mod 8 = 1 -> conflict-free LDS.128
constexpr int SW_STRIDE = 20;             // padded influence row
constexpr float INV_EXT = 1.0f / 0.6f;

// ---- device-global scratch / tables (no allocation allowed) ----
__device__ float g_wf[ROWS_TOT * KC];                 // stage-1 output, [na][kc]
__device__ float4 g_kp4[A * 16];                      // (r0,r1,r2,|kp|^2) per (a,k)
__device__ unsigned long long g_wp[(KC / 2) * COUT];  // (W[2p][d], W[2p+1][d]) packed

// ---- packed f32x2 helpers (bit-identical to scalar fp32 FMA) ----
__device__ __forceinline__ void fma2(unsigned long long& acc,
                                     unsigned long long a, unsigned long long b) {
    asm("fma.rn.f32x2 %0, %1, %2, %0;" : "+l"(acc) : "l"(a), "l"(b));
}
__device__ __forceinline__ unsigned long long dup2(float x) {
    unsigned long long r;
    asm("mov.b64 %0, {%1, %1};" : "=l"(r) : "f"(x));
    return r;
}
__device__ __forceinline__ float lo32(unsigned long long v) {
    float a, b; asm("mov.b64 {%0, %1}, %2;" : "=f"(a), "=f"(b) : "l"(v)); return a;
}
__device__ __forceinline__ float hi32(unsigned long long v) {
    float a, b; asm("mov.b64 {%0, %1}, %2;" : "=f"(a), "=f"(b) : "l"(v)); return b;
}

// ---- precompute: rotated kernel points + packed weight pairs (parallel) ----
__global__ void precompute_kernel(const float* __restrict__ kp,
                                  const float* __restrict__ anchors,
                                  const float* __restrict__ weights) {
    int gid = blockIdx.x * blockDim.x + threadIdx.x;
    if (gid < A * K) {
        int a = gid / K;
        int k = gid - a * K;
        float p0 = kp[k * 3 + 0], p1 = kp[k * 3 + 1], p2 = kp[k * 3 + 2];
        const float* R = anchors + a * 9;
        float r0 = R[0] * p0 + R[1] * p1 + R[2] * p2;
        float r1 = R[3] * p0 + R[4] * p1 + R[5] * p2;
        float r2 = R[6] * p0 + R[7] * p1 + R[8] * p2;
        g_kp4[a * 16 + k] = make_float4(r0, r1, r2, r0 * r0 + r1 * r1 + r2 * r2);
    }
    // pack weights: Wp[p][d] = (W[2p][d], W[2p+1][d])
    if (gid < (KC / 2) * COUT) {
        int p = gid >> 5;
        int d = gid & 31;
        float lo = weights[(2 * p) * COUT + d];
        float hi = weights[(2 * p + 1) * COUT + d];
        unsigned long long v;
        asm("mov.b64 %0, {%1, %2};" : "=l"(v) : "f"(lo), "f"(hi));
        g_wp[gid] = v;
    }
}

// =====================  Kernel A: stages 0+1  =====================
// 256 threads = 8 warps; warp w owns query blockIdx.x*8+w, loops 4 anchors.
// Writes wf[na][kc] (kc = k*32+c) to global scratch, coalesced.
__global__ __launch_bounds__(256, 3) void stage1_kernel(
    const float* __restrict__ q_pts,
    const float* __restrict__ s_pts,
    const int*   __restrict__ nbr,
    const float* __restrict__ x)
{
    __shared__ float4 s_kp[A * 16];
    __shared__ float  s_w[QB][NB][SW_STRIDE];
    __shared__ int    s_off[QB][NB];       // precomputed x row offsets (m*128)

    const int tid  = threadIdx.x;
    const int w    = tid >> 5;
    const int lane = tid & 31;
    const int q    = blockIdx.x * QB + w;

    if (tid < A * K) {
        int a = tid / K;
        int k = tid - a * K;
        s_kp[a * 16 + k] = g_kp4[a * 16 + k];
    }

    // stage 0: gather + center (lane = neighbor b)
    int m = nbr[q * NB + lane];
    s_off[w][lane] = m * (A * CIN);
    float dx = s_pts[m * 3 + 0] - q_pts[q * 3 + 0];
    float dy = s_pts[m * 3 + 1] - q_pts[q * 3 + 1];
    float dz = s_pts[m * 3 + 2] - q_pts[q * 3 + 2];
    float n2 = dx * dx + dy * dy + dz * dz;
    __syncthreads();

    #pragma unroll 1
    for (int a = 0; a < A; a++) {
        // influence weights (lane = b)
        {
            float wk[16];
            #pragma unroll
            for (int k = 0; k < K; k++) {
                float4 g = s_kp[a * 16 + k];
                float cross = dx * g.x + dy * g.y + dz * g.z;
                float sq = fmaxf(fmaf(-2.0f, cross, n2 + g.w), 1e-12f);
                wk[k] = fmaxf(1.0f - sqrtf(sq) * INV_EXT, 0.0f);
            }
            wk[15] = 0.0f;
            float4* dst = (float4*)&s_w[w][lane][0];
            dst[0] = make_float4(wk[0],  wk[1],  wk[2],  wk[3]);
            dst[1] = make_float4(wk[4],  wk[5],  wk[6],  wk[7]);
            dst[2] = make_float4(wk[8],  wk[9],  wk[10], wk[11]);
            dst[3] = make_float4(wk[12], wk[13], wk[14], wk[15]);
        }
        __syncwarp();

        // stage 1 (lane = channel c); accumulators pack (k, k+1)
        // unroll 2 ONLY: keeps the live ulonglong2 window small -> no spills
        unsigned long long wf2[8];
        #pragma unroll
        for (int j = 0; j < 8; j++) wf2[j] = 0ULL;

        const float* xa = x + a * CIN + lane;
        #pragma unroll 2
        for (int b = 0; b < NB; b++) {
            float xv = __ldg(xa + s_off[w][b]);
            unsigned long long xv2 = dup2(xv);
            const ulonglong2* wp = (const ulonglong2*)&s_w[w][b][0];
            ulonglong2 p0 = wp[0], p1 = wp[1];
            fma2(wf2[0], p0.x, xv2);
            fma2(wf2[1], p0.y, xv2);
            fma2(wf2[2], p1.x, xv2);
            fma2(wf2[3], p1.y, xv2);
            ulonglong2 p2 = wp[2], p3 = wp[3];
            fma2(wf2[4], p2.x, xv2);
            fma2(wf2[5], p2.y, xv2);
            fma2(wf2[6], p3.x, xv2);
            fma2(wf2[7], p3.y, xv2);
        }

        // store wf[na][k*32 + lane], coalesced (k=15 is pad, not stored)
        float* dst = g_wf + (q * A + a) * KC + lane;
        #pragma unroll
        for (int j = 0; j < 7; j++) {
            dst[(2 * j) * CIN]     = lo32(wf2[j]);
            dst[(2 * j + 1) * CIN] = hi32(wf2[j]);
        }
        dst[14 * CIN] = lo32(wf2[7]);
        __syncwarp();   // protect s_w before next anchor overwrites it
    }
}

// =====================  Kernel B: stage-2 GEMM  =====================
// [64000 x 480] @ [480 x 32]. Block = 32 rows, 256 threads = 8 warps.
// lane = row, warp w owns cols 4w..4w+3. Per 4 kc:
//   1 LDS.128 (wf pairs) + 4 LDG.128 (packed weights, L1-resident) + 8 FFMA2.
__global__ __launch_bounds__(256, 3) void stage2_kernel(float* __restrict__ out)
{
    extern __shared__ float st[];   // [RB][WF_PAD]

    const int tid  = threadIdx.x;
    const int w    = tid >> 5;
    const int lane = tid & 31;

    // cooperative coalesced tile load: 32 rows x 480 floats = 3840 float4
    {
        const float4* src = (const float4*)(g_wf + (long)blockIdx.x * RB * KC);
        #pragma unroll
        for (int j = 0; j < 15; j++) {
            int i   = tid + j * 256;
            int row = i / 120;
            int c4  = i - row * 120;
            ((float4*)st)[row * (WF_PAD / 4) + c4] = __ldcs(src + i);
        }
    }
    __syncthreads();

    const int dc = w * 4;
    const ulonglong2* fw = (const ulonglong2*)(st + lane * WF_PAD);
    const unsigned long long* wp = g_wp;

    unsigned long long a0e = 0, a1e = 0, a2e = 0, a3e = 0;
    unsigned long long a0o = 0, a1o = 0, a2o = 0, a3o = 0;

    // unroll 2 ONLY: live window = 2*(f + 4 weight u64x2) ~ 40 regs + 16 acc
    #pragma unroll 2
    for (int kq = 0; kq < KC / 4; kq++) {
        ulonglong2 f = fw[kq];   // (wf[4kq],wf[4kq+1]) , (wf[4kq+2],wf[4kq+3])
        ulonglong2 we = *(const ulonglong2*)(wp + (2 * kq) * COUT + dc);
        ulonglong2 wE = *(const ulonglong2*)(wp + (2 * kq) * COUT + dc + 2);
        fma2(a0e, f.x, we.x);
        fma2(a1e, f.x, we.y);
        fma2(a2e, f.x, wE.x);
        fma2(a3e, f.x, wE.y);
        ulonglong2 wo = *(const ulonglong2*)(wp + (2 * kq + 1) * COUT + dc);
        ulonglong2 wO = *(const ulonglong2*)(wp + (2 * kq + 1) * COUT + dc + 2);
        fma2(a0o, f.y, wo.x);
        fma2(a1o, f.y, wo.y);
        fma2(a2o, f.y, wO.x);
        fma2(a3o, f.y, wO.y);
    }

    float4 o;
    o.x = (lo32(a0e) + hi32(a0e)) + (lo32(a0o) + hi32(a0o));
    o.y = (lo32(a1e) + hi32(a1e)) + (lo32(a1o) + hi32(a1o));
    o.z = (lo32(a2e) + hi32(a2e)) + (lo32(a2o) + hi32(a2o));
    o.w = (lo32(a3e) + hi32(a3e)) + (lo32(a3o) + hi32(a3o));
    *(float4*)(out + ((long)blockIdx.x * RB + lane) * COUT + dc) = o;
}

extern "C" void kernel_launch(void* const* d_in, const int* in_sizes, int n_in,
                              void* d_out, int out_size) {
    const float* q_pts   = (const float*)d_in[0];
    const float* s_pts   = (const float*)d_in[1];
    const int*   nbr     = (const int*)  d_in[2];
    const float* x       = (const float*)d_in[3];
    const float* kp      = (const float*)d_in[4];
    const float* anchors = (const float*)d_in[5];
    const float* weights = (const float*)d_in[6];
    float* out = (float*)d_out;

    const int Nq = in_sizes[2] / NB;   // 16000

    constexpr size_t smemB = (size_t)RB * WF_PAD * sizeof(float);   // 61952 B
    static bool attr_set = false;
    if (!attr_set) {
        cudaFuncSetAttribute(stage2_kernel,
                             cudaFuncAttributeMaxDynamicSharedMemorySize,
                             (int)smemB);
        attr_set = true;
    }

    precompute_kernel<<<32, 256>>>(kp, anchors, weights);
    stage1_kernel<<<Nq / QB, 256>>>(q_pts, s_pts, nbr, x);
    stage2_kernel<<<(Nq * A) / RB, 256, smemB>>>(out);
}

// round 7
// speedup vs baseline: 1.0791x; 1.0791x over previous
#include <cuda_runtime.h>

// Problem constants (fixed by the reference)
constexpr int NB   = 32;   // neighbors per query
constexpr int A    = 4;    // anchors
constexpr int K    = 15;   // kernel points
constexpr int CIN  = 32;
constexpr int COUT = 32;
constexpr int NQ   = 16000;
constexpr int ROWS_TOT = NQ * A;          // 64000 (n,a) rows
constexpr int KC   = K * CIN;             // 480 reduction length
constexpr int QB   = 8;                   // queries per block (stage 1)
constexpr int RB   = 32;                  // rows per block (stage 2)
constexpr int WF_PAD = KC + 4;            // 484 floats: float4 stride 121 (odd) -> conflict-free LDS.128
constexpr int SW_STRIDE = 20;             // padded influence row
constexpr float INV_EXT = 1.0f / 0.6f;

// ---- device-global scratch / tables (no allocation allowed) ----
__device__ float g_wf[ROWS_TOT * KC];                 // stage-1 output, [na][kc]
__device__ unsigned long long g_wp[(KC / 2) * COUT];  // (W[2p][d], W[2p+1][d]) packed

// ---- packed f32x2 helpers (bit-identical to scalar fp32 FMA) ----
__device__ __forceinline__ void fma2(unsigned long long& acc,
                                     unsigned long long a, unsigned long long b) {
    asm("fma.rn.f32x2 %0, %1, %2, %0;" : "+l"(acc) : "l"(a), "l"(b));
}
__device__ __forceinline__ unsigned long long dup2(float x) {
    unsigned long long r;
    asm("mov.b64 %0, {%1, %1};" : "=l"(r) : "f"(x));
    return r;
}
__device__ __forceinline__ float lo32(unsigned long long v) {
    float a, b; asm("mov.b64 {%0, %1}, %2;" : "=f"(a), "=f"(b) : "l"(v)); return a;
}
__device__ __forceinline__ float hi32(unsigned long long v) {
    float a, b; asm("mov.b64 {%0, %1}, %2;" : "=f"(a), "=f"(b) : "l"(v)); return b;
}

// =====================  Kernel 1 (launched FIRST): stages 0+1  =====================
// 256 threads = 8 warps; warp w owns query blockIdx.x*8+w, loops 4 anchors.
// Computes its own rotated-KP table (no precompute dependency) so it can be
// the first launch -> ncu's fixed capture slot lands here.
__global__ __launch_bounds__(256, 3) void stage1_kernel(
    const float* __restrict__ q_pts,
    const float* __restrict__ s_pts,
    const int*   __restrict__ nbr,
    const float* __restrict__ x,
    const float* __restrict__ kp,
    const float* __restrict__ anchors)
{
    __shared__ float4 s_kp[A * 16];        // (r0,r1,r2,|kp|^2)
    __shared__ float  s_w[QB][NB][SW_STRIDE];
    __shared__ int    s_off[QB][NB];       // x row offsets (m*128)

    const int tid  = threadIdx.x;
    const int w    = tid >> 5;
    const int lane = tid & 31;
    const int q    = blockIdx.x * QB + w;

    // local rotated-KP table (60 tiny rotations, once per block)
    if (tid < A * K) {
        int a = tid / K;
        int k = tid - a * K;
        float p0 = kp[k * 3 + 0], p1 = kp[k * 3 + 1], p2 = kp[k * 3 + 2];
        const float* R = anchors + a * 9;
        float r0 = R[0] * p0 + R[1] * p1 + R[2] * p2;
        float r1 = R[3] * p0 + R[4] * p1 + R[5] * p2;
        float r2 = R[6] * p0 + R[7] * p1 + R[8] * p2;
        s_kp[a * 16 + k] = make_float4(r0, r1, r2, r0 * r0 + r1 * r1 + r2 * r2);
    }

    // stage 0: gather + center (lane = neighbor b)
    int m = nbr[q * NB + lane];
    s_off[w][lane] = m * (A * CIN);
    float dx = s_pts[m * 3 + 0] - q_pts[q * 3 + 0];
    float dy = s_pts[m * 3 + 1] - q_pts[q * 3 + 1];
    float dz = s_pts[m * 3 + 2] - q_pts[q * 3 + 2];
    float n2 = dx * dx + dy * dy + dz * dz;
    __syncthreads();

    #pragma unroll 1
    for (int a = 0; a < A; a++) {
        // influence weights (lane = b)
        {
            float wk[16];
            #pragma unroll
            for (int k = 0; k < K; k++) {
                float4 g = s_kp[a * 16 + k];
                float cross = dx * g.x + dy * g.y + dz * g.z;
                float sq = fmaxf(fmaf(-2.0f, cross, n2 + g.w), 1e-12f);
                wk[k] = fmaxf(1.0f - sqrtf(sq) * INV_EXT, 0.0f);
            }
            wk[15] = 0.0f;
            float4* dst = (float4*)&s_w[w][lane][0];
            dst[0] = make_float4(wk[0],  wk[1],  wk[2],  wk[3]);
            dst[1] = make_float4(wk[4],  wk[5],  wk[6],  wk[7]);
            dst[2] = make_float4(wk[8],  wk[9],  wk[10], wk[11]);
            dst[3] = make_float4(wk[12], wk[13], wk[14], wk[15]);
        }
        __syncwarp();

        // stage 1 (lane = channel c); accumulators pack (k, k+1)
        // unroll 8: MLP=8 on the x-gather -> covers L2 latency at occ 3
        unsigned long long wf2[8];
        #pragma unroll
        for (int j = 0; j < 8; j++) wf2[j] = 0ULL;

        const float* xa = x + a * CIN + lane;
        #pragma unroll 8
        for (int b = 0; b < NB; b++) {
            float xv = __ldg(xa + s_off[w][b]);
            unsigned long long xv2 = dup2(xv);
            const ulonglong2* wp = (const ulonglong2*)&s_w[w][b][0];
            ulonglong2 p0 = wp[0], p1 = wp[1], p2 = wp[2], p3 = wp[3];
            fma2(wf2[0], p0.x, xv2);
            fma2(wf2[1], p0.y, xv2);
            fma2(wf2[2], p1.x, xv2);
            fma2(wf2[3], p1.y, xv2);
            fma2(wf2[4], p2.x, xv2);
            fma2(wf2[5], p2.y, xv2);
            fma2(wf2[6], p3.x, xv2);
            fma2(wf2[7], p3.y, xv2);
        }

        // store wf[na][k*32 + lane], coalesced (k=15 is pad, not stored)
        float* dst = g_wf + (q * A + a) * KC + lane;
        #pragma unroll
        for (int j = 0; j < 7; j++) {
            dst[(2 * j) * CIN]     = lo32(wf2[j]);
            dst[(2 * j + 1) * CIN] = hi32(wf2[j]);
        }
        dst[14 * CIN] = lo32(wf2[7]);
        __syncwarp();   // protect s_w before next anchor overwrites it
    }
}

// ---- precompute (second launch): pack weight pairs only ----
__global__ void precompute_kernel(const float* __restrict__ weights) {
    int gid = blockIdx.x * blockDim.x + threadIdx.x;
    if (gid < (KC / 2) * COUT) {
        int p = gid >> 5;
        int d = gid & 31;
        float lo = weights[(2 * p) * COUT + d];
        float hi = weights[(2 * p + 1) * COUT + d];
        unsigned long long v;
        asm("mov.b64 %0, {%1, %2};" : "=l"(v) : "f"(lo), "f"(hi));
        g_wp[gid] = v;
    }
}

// =====================  Kernel 3: stage-2 GEMM  =====================
// [64000 x 480] @ [480 x 32]. Block = 32 rows, 256 threads = 8 warps.
// lane = row, warp w owns cols 4w..4w+3. Per 4 kc:
//   1 LDS.128 (wf pairs) + 4 LDG.128 (packed weights, L1-resident) + 8 FFMA2.
__global__ __launch_bounds__(256, 3) void stage2_kernel(float* __restrict__ out)
{
    extern __shared__ float st[];   // [RB][WF_PAD]

    const int tid  = threadIdx.x;
    const int w    = tid >> 5;
    const int lane = tid & 31;

    // cooperative coalesced tile load: 32 rows x 480 floats = 3840 float4
    {
        const float4* src = (const float4*)(g_wf + (long)blockIdx.x * RB * KC);
        #pragma unroll
        for (int j = 0; j < 15; j++) {
            int i   = tid + j * 256;
            int row = i / 120;
            int c4  = i - row * 120;
            ((float4*)st)[row * (WF_PAD / 4) + c4] = __ldcs(src + i);
        }
    }
    __syncthreads();

    const int dc = w * 4;
    const ulonglong2* fw = (const ulonglong2*)(st + lane * WF_PAD);
    const unsigned long long* wp = g_wp;

    unsigned long long a0e = 0, a1e = 0, a2e = 0, a3e = 0;
    unsigned long long a0o = 0, a1o = 0, a2o = 0, a3o = 0;

    #pragma unroll 4
    for (int kq = 0; kq < KC / 4; kq++) {
        ulonglong2 f = fw[kq];   // (wf[4kq],wf[4kq+1]) , (wf[4kq+2],wf[4kq+3])
        ulonglong2 we = *(const ulonglong2*)(wp + (2 * kq) * COUT + dc);
        ulonglong2 wE = *(const ulonglong2*)(wp + (2 * kq) * COUT + dc + 2);
        ulonglong2 wo = *(const ulonglong2*)(wp + (2 * kq + 1) * COUT + dc);
        ulonglong2 wO = *(const ulonglong2*)(wp + (2 * kq + 1) * COUT + dc + 2);
        fma2(a0e, f.x, we.x);
        fma2(a1e, f.x, we.y);
        fma2(a2e, f.x, wE.x);
        fma2(a3e, f.x, wE.y);
        fma2(a0o, f.y, wo.x);
        fma2(a1o, f.y, wo.y);
        fma2(a2o, f.y, wO.x);
        fma2(a3o, f.y, wO.y);
    }

    float4 o;
    o.x = (lo32(a0e) + hi32(a0e)) + (lo32(a0o) + hi32(a0o));
    o.y = (lo32(a1e) + hi32(a1e)) + (lo32(a1o) + hi32(a1o));
    o.z = (lo32(a2e) + hi32(a2e)) + (lo32(a2o) + hi32(a2o));
    o.w = (lo32(a3e) + hi32(a3e)) + (lo32(a3o) + hi32(a3o));
    *(float4*)(out + ((long)blockIdx.x * RB + lane) * COUT + dc) = o;
}

extern "C" void kernel_launch(void* const* d_in, const int* in_sizes, int n_in,
                              void* d_out, int out_size) {
    const float* q_pts   = (const float*)d_in[0];
    const float* s_pts   = (const float*)d_in[1];
    const int*   nbr     = (const int*)  d_in[2];
    const float* x       = (const float*)d_in[3];
    const float* kp      = (const float*)d_in[4];
    const float* anchors = (const float*)d_in[5];
    const float* weights = (const float*)d_in[6];
    float* out = (float*)d_out;

    const int Nq = in_sizes[2] / NB;   // 16000

    constexpr size_t smemB = (size_t)RB * WF_PAD * sizeof(float);   // 61952 B
    static bool attr_set = false;
    if (!attr_set) {
        cudaFuncSetAttribute(stage2_kernel,
                             cudaFuncAttributeMaxDynamicSharedMemorySize,
                             (int)smemB);
        attr_set = true;
    }

    // stage1 first so the ncu capture slot (first launch of a call) profiles it
    stage1_kernel<<<Nq / QB, 256>>>(q_pts, s_pts, nbr, x, kp, anchors);
    precompute_kernel<<<30, 256>>>(weights);
    stage2_kernel<<<(Nq * A) / RB, 256, smemB>>>(out);
}

// round 8
// speedup vs baseline: 1.3796x; 1.2785x over previous
#include <cuda_runtime.h>

// Problem constants (fixed by the reference)
constexpr int NB   = 32;   // neighbors per query
constexpr int A    = 4;    // anchors
constexpr int K    = 15;   // kernel points
constexpr int CIN  = 32;
constexpr int COUT = 32;
constexpr int NQ   = 16000;
constexpr int KC   = K * CIN;            // 480
constexpr int QB   = 8;                  // queries per block (stage 1)
constexpr int NT   = NQ * A / 32;        // 2000 stage-2 tiles (32 rows each)
constexpr int WF_PADF = KC + 4;          // 484 floats: float4 stride 121 (odd) -> conflict-free
constexpr float INV_EXT = 1.0f / 0.6f;

// ---- device-global scratch / tables ----
__device__ float g_wf[NQ * A * KC];                   // stage-1 output, [na][kc]
__device__ unsigned long long g_wp[(KC / 2) * COUT];  // (W[2p][d], W[2p+1][d]) packed

// ---- packed f32x2 helpers (bit-identical to scalar fp32 FMA) ----
__device__ __forceinline__ void fma2(unsigned long long& acc,
                                     unsigned long long a, unsigned long long b) {
    asm("fma.rn.f32x2 %0, %1, %2, %0;" : "+l"(acc) : "l"(a), "l"(b));
}
__device__ __forceinline__ unsigned long long dup2(float x) {
    unsigned long long r;
    asm("mov.b64 %0, {%1, %1};" : "=l"(r) : "f"(x));
    return r;
}
__device__ __forceinline__ float lo32(unsigned long long v) {
    float a, b; asm("mov.b64 {%0, %1}, %2;" : "=f"(a), "=f"(b) : "l"(v)); return a;
}
__device__ __forceinline__ float hi32(unsigned long long v) {
    float a, b; asm("mov.b64 {%0, %1}, %2;" : "=f"(a), "=f"(b) : "l"(v)); return b;
}
__device__ __forceinline__ unsigned s2u(const void* p) {
    unsigned r;
    asm("{ .reg .u64 t; cvta.to.shared.u64 t, %1; cvt.u32.u64 %0, t; }"
        : "=r"(r) : "l"(p));
    return r;
}

// =====================  Kernel 1 (FIRST launch): stages 0+1  =====================
// 256 threads = 8 warps; warp w owns query blockIdx.x*8+w.
// Single b-loop covering ALL 4 anchors: lane = (anchor = lane>>3, c4 = (lane&7)*4).
// Per b: 1 coalesced LDG.128 (full 512B x row) + 4 phase-uniform LDS.128 + 32 FFMA2.
constexpr int S1_W2F   = QB * NB * 68;                       // influence smem, floats
constexpr int S1_SMEMB = S1_W2F * 4 + 64 * 16 + QB * 32 * 4; // + s_kp + s_addr

__global__ __launch_bounds__(256, 2) void stage1_kernel(
    const float* __restrict__ q_pts,
    const float* __restrict__ s_pts,
    const int*   __restrict__ nbr,
    const float* __restrict__ x,
    const float* __restrict__ kp,
    const float* __restrict__ anchors)
{
    extern __shared__ float sm[];
    float*  s_w2   = sm;                          // [8 warps][32 b][68] (a*16+k inside)
    float4* s_kp   = (float4*)(sm + S1_W2F);      // [A*16] (r0,r1,r2,|kp|^2)
    int*    s_addr = (int*)(sm + S1_W2F + 64 * 4);// [8 warps][32 b] x float4-offsets

    const int tid  = threadIdx.x;
    const int w    = tid >> 5;
    const int lane = tid & 31;
    const int q    = blockIdx.x * QB + w;

    // rotated-KP table (60 tiny rotations, once per block)
    if (tid < A * K) {
        int a = tid / K;
        int k = tid - a * K;
        float p0 = kp[k * 3 + 0], p1 = kp[k * 3 + 1], p2 = kp[k * 3 + 2];
        const float* R = anchors + a * 9;
        float r0 = R[0] * p0 + R[1] * p1 + R[2] * p2;
        float r1 = R[3] * p0 + R[4] * p1 + R[5] * p2;
        float r2 = R[6] * p0 + R[7] * p1 + R[8] * p2;
        s_kp[a * 16 + k] = make_float4(r0, r1, r2, r0 * r0 + r1 * r1 + r2 * r2);
    }

    // stage 0: gather + center (lane = neighbor b)
    int m = nbr[q * NB + lane];
    s_addr[w * 32 + lane] = m * 32;     // float4 units (row = 128 floats)
    float dx = s_pts[m * 3 + 0] - q_pts[q * 3 + 0];
    float dy = s_pts[m * 3 + 1] - q_pts[q * 3 + 1];
    float dz = s_pts[m * 3 + 2] - q_pts[q * 3 + 2];
    float n2 = dx * dx + dy * dy + dz * dz;
    __syncthreads();   // s_kp ready

    // phase A: influence weights for ALL anchors (lane = b)
    float* swq = s_w2 + w * (NB * 68);
    #pragma unroll
    for (int a = 0; a < A; a++) {
        float wk[16];
        #pragma unroll
        for (int k = 0; k < K; k++) {
            float4 g = s_kp[a * 16 + k];
            float cross = dx * g.x + dy * g.y + dz * g.z;
            float sq = fmaxf(fmaf(-2.0f, cross, n2 + g.w), 1e-12f);
            wk[k] = fmaxf(1.0f - sqrtf(sq) * INV_EXT, 0.0f);
        }
        wk[15] = 0.0f;
        float4* dst = (float4*)(swq + lane * 68 + a * 16);
        dst[0] = make_float4(wk[0],  wk[1],  wk[2],  wk[3]);
        dst[1] = make_float4(wk[4],  wk[5],  wk[6],  wk[7]);
        dst[2] = make_float4(wk[8],  wk[9],  wk[10], wk[11]);
        dst[3] = make_float4(wk[12], wk[13], wk[14], wk[15]);
    }
    __syncwarp();

    // phase B: single b-loop over all anchors.
    // acc[c][j] packs (wf[2j][c], wf[2j+1][c]) for this lane's anchor.
    unsigned long long acc[4][8];
    #pragma unroll
    for (int c = 0; c < 4; c++)
        #pragma unroll
        for (int j = 0; j < 8; j++) acc[c][j] = 0ULL;

    const float4* xrow   = (const float4*)x;
    const int*    myaddr = s_addr + w * 32;
    const float*  wkbase = swq + (lane >> 3) * 16;   // this lane's anchor slice

    #pragma unroll 2
    for (int b = 0; b < NB; b++) {
        float4 xq = __ldg(xrow + myaddr[b] + lane);   // warp covers full 512B row
        const ulonglong2* wp = (const ulonglong2*)(wkbase + b * 68);
        ulonglong2 k01 = wp[0], k23 = wp[1], k45 = wp[2], k67 = wp[3];
        unsigned long long d0 = dup2(xq.x), d1 = dup2(xq.y),
                           d2 = dup2(xq.z), d3 = dup2(xq.w);
        fma2(acc[0][0], k01.x, d0); fma2(acc[0][1], k01.y, d0);
        fma2(acc[0][2], k23.x, d0); fma2(acc[0][3], k23.y, d0);
        fma2(acc[0][4], k45.x, d0); fma2(acc[0][5], k45.y, d0);
        fma2(acc[0][6], k67.x, d0); fma2(acc[0][7], k67.y, d0);
        fma2(acc[1][0], k01.x, d1); fma2(acc[1][1], k01.y, d1);
        fma2(acc[1][2], k23.x, d1); fma2(acc[1][3], k23.y, d1);
        fma2(acc[1][4], k45.x, d1); fma2(acc[1][5], k45.y, d1);
        fma2(acc[1][6], k67.x, d1); fma2(acc[1][7], k67.y, d1);
        fma2(acc[2][0], k01.x, d2); fma2(acc[2][1], k01.y, d2);
        fma2(acc[2][2], k23.x, d2); fma2(acc[2][3], k23.y, d2);
        fma2(acc[2][4], k45.x, d2); fma2(acc[2][5], k45.y, d2);
        fma2(acc[2][6], k67.x, d2); fma2(acc[2][7], k67.y, d2);
        fma2(acc[3][0], k01.x, d3); fma2(acc[3][1], k01.y, d3);
        fma2(acc[3][2], k23.x, d3); fma2(acc[3][3], k23.y, d3);
        fma2(acc[3][4], k45.x, d3); fma2(acc[3][5], k45.y, d3);
        fma2(acc[3][6], k67.x, d3); fma2(acc[3][7], k67.y, d3);
    }

    // store wf: lane's anchor row, 4 channels, 15 k's (k=15 pad dropped)
    {
        const int a  = lane >> 3;
        const int c4 = (lane & 7) * 4;
        float* dst = g_wf + ((long)(q * A + a)) * KC + c4;
        #pragma unroll
        for (int j = 0; j < 8; j++) {
            *(float4*)(dst + (2 * j) * CIN) =
                make_float4(lo32(acc[0][j]), lo32(acc[1][j]),
                            lo32(acc[2][j]), lo32(acc[3][j]));
            if (j < 7) {
                *(float4*)(dst + (2 * j + 1) * CIN) =
                    make_float4(hi32(acc[0][j]), hi32(acc[1][j]),
                                hi32(acc[2][j]), hi32(acc[3][j]));
            }
        }
    }
}

// ---- precompute (second launch): pack weight pairs ----
__global__ void precompute_kernel(const float* __restrict__ weights) {
    int gid = blockIdx.x * blockDim.x + threadIdx.x;
    if (gid < (KC / 2) * COUT) {
        int p = gid >> 5;
        int d = gid & 31;
        float lo = weights[(2 * p) * COUT + d];
        float hi = weights[(2 * p + 1) * COUT + d];
        unsigned long long v;
        asm("mov.b64 %0, {%1, %2};" : "=l"(v) : "f"(lo), "f"(hi));
        g_wp[gid] = v;
    }
}

// =====================  Kernel 3: persistent stage-2 GEMM  =====================
// [64000 x 480] @ [480 x 32]. 152 persistent blocks x 512 threads, 1 block/SM.
// Weights live in smem (loaded once); wf tiles double-buffered via cp.async.
// 16 warps = 8 col-groups x 2 kc-halves; smem partial combine.
constexpr int S2_WU   = (KC / 2) * COUT;          // 7680 u64 packed weights
constexpr int S2_TILE = 32 * WF_PADF;             // one wf tile, floats
constexpr int S2_PART = 2 * 32 * 9 * 4;           // partials [h][row][9 pad] float4, floats
constexpr int S2_SMEMB = S2_WU * 8 + 2 * S2_TILE * 4 + S2_PART * 4;   // 194560 B

__device__ __forceinline__ void load_tile_async(float* dst, const float* src, int tid) {
    #pragma unroll
    for (int j = 0; j < 8; j++) {
        int i = tid + j * 512;
        if (i < 3840) {                      // 32 rows * 120 float4
            int row = i / 120;
            int c4  = i - row * 120;
            asm volatile("cp.async.ca.shared.global [%0], [%1], 16;"
                         :: "r"(s2u(dst + row * WF_PADF + c4 * 4)),
                            "l"((const float4*)src + i) : "memory");
        }
    }
}

__global__ __launch_bounds__(512, 1) void stage2_kernel(float* __restrict__ out)
{
    extern __shared__ float sm2[];
    unsigned long long* sw = (unsigned long long*)sm2;          // [7680]
    float*  st   = sm2 + S2_WU * 2;                             // 2 tiles
    float4* part = (float4*)(sm2 + S2_WU * 2 + 2 * S2_TILE);    // [2][32][9]

    const int tid  = threadIdx.x;
    const int w    = tid >> 5;
    const int lane = tid & 31;
    const int g    = w & 7;        // col-group: cols 4g..4g+3
    const int h    = w >> 3;       // kc half
    const int dc   = g * 4;

    // weights -> smem (once)
    for (int i = tid; i < S2_WU; i += 512) sw[i] = g_wp[i];

    // prime buffer 0
    load_tile_async(st, g_wf + (long)blockIdx.x * 32 * KC, tid);
    asm volatile("cp.async.commit_group;" ::: "memory");

    const unsigned long long* wpB = sw + (h * 120) * COUT;

    int cur = 0;
    for (int t = blockIdx.x; t < NT; t += gridDim.x) {
        int tn = t + gridDim.x;
        if (tn < NT)
            load_tile_async(st + (cur ^ 1) * S2_TILE, g_wf + (long)tn * 32 * KC, tid);
        asm volatile("cp.async.commit_group;" ::: "memory");
        asm volatile("cp.async.wait_group 1;" ::: "memory");
        __syncthreads();   // tile cur ready; also protects part/buffers across iters

        const float* fw = st + cur * S2_TILE + lane * WF_PADF + h * 240;

        unsigned long long a0e = 0, a1e = 0, a2e = 0, a3e = 0;
        unsigned long long a0o = 0, a1o = 0, a2o = 0, a3o = 0;

        #pragma unroll 2
        for (int kq = 0; kq < 60; kq++) {
            ulonglong2 f = *(const ulonglong2*)(fw + kq * 4);
            const unsigned long long* we_p = wpB + (2 * kq) * COUT + dc;
            const unsigned long long* wo_p = wpB + (2 * kq + 1) * COUT + dc;
            ulonglong2 we = *(const ulonglong2*)(we_p);
            ulonglong2 wE = *(const ulonglong2*)(we_p + 2);
            ulonglong2 wo = *(const ulonglong2*)(wo_p);
            ulonglong2 wO = *(const ulonglong2*)(wo_p + 2);
            fma2(a0e, f.x, we.x);
            fma2(a1e, f.x, we.y);
            fma2(a2e, f.x, wE.x);
            fma2(a3e, f.x, wE.y);
            fma2(a0o, f.y, wo.x);
            fma2(a1o, f.y, wo.y);
            fma2(a2o, f.y, wO.x);
            fma2(a3o, f.y, wO.y);
        }

        float4 o;
        o.x = (lo32(a0e) + hi32(a0e)) + (lo32(a0o) + hi32(a0o));
        o.y = (lo32(a1e) + hi32(a1e)) + (lo32(a1o) + hi32(a1o));
        o.z = (lo32(a2e) + hi32(a2e)) + (lo32(a2o) + hi32(a2o));
        o.w = (lo32(a3e) + hi32(a3e)) + (lo32(a3o) + hi32(a3o));
        part[h * 32 * 9 + lane * 9 + g] = o;
        __syncthreads();

        if (tid < 256) {
            int row = tid >> 3;
            int g2  = tid & 7;
            float4 v0 = part[row * 9 + g2];
            float4 v1 = part[32 * 9 + row * 9 + g2];
            float4 v = make_float4(v0.x + v1.x, v0.y + v1.y,
                                   v0.z + v1.z, v0.w + v1.w);
            *(float4*)(out + ((long)t * 32 + row) * COUT + g2 * 4) = v;
        }
        cur ^= 1;
    }
}

extern "C" void kernel_launch(void* const* d_in, const int* in_sizes, int n_in,
                              void* d_out, int out_size) {
    const float* q_pts   = (const float*)d_in[0];
    const float* s_pts   = (const float*)d_in[1];
    const int*   nbr     = (const int*)  d_in[2];
    const float* x       = (const float*)d_in[3];
    const float* kp      = (const float*)d_in[4];
    const float* anchors = (const float*)d_in[5];
    const float* weights = (const float*)d_in[6];
    float* out = (float*)d_out;

    const int Nq = in_sizes[2] / NB;   // 16000

    static bool attr_set = false;
    if (!attr_set) {
        cudaFuncSetAttribute(stage1_kernel,
                             cudaFuncAttributeMaxDynamicSharedMemorySize, S1_SMEMB);
        cudaFuncSetAttribute(stage2_kernel,
                             cudaFuncAttributeMaxDynamicSharedMemorySize, S2_SMEMB);
        attr_set = true;
    }

    // stage1 first so the ncu capture slot profiles it
    stage1_kernel<<<Nq / QB, 256, S1_SMEMB>>>(q_pts, s_pts, nbr, x, kp, anchors);
    precompute_kernel<<<30, 256>>>(weights);
    stage2_kernel<<<152, 512, S2_SMEMB>>>(out);
}

// round 9
// speedup vs baseline: 1.5919x; 1.1539x over previous
#include <cuda_runtime.h>

// Problem constants (fixed by the reference)
constexpr int NB   = 32;   // neighbors per query
constexpr int A    = 4;    // anchors
constexpr int K    = 15;   // kernel points
constexpr int CIN  = 32;
constexpr int COUT = 32;
constexpr int NQ   = 16000;
constexpr int KC   = K * CIN;            // 480
constexpr int QB   = 8;                  // queries per block (stage 1)
constexpr int NPAIR = NQ * A / 64;       // 1000 stage-2 passes (64 rows each)
constexpr int WF_PADF = KC + 4;          // 484 floats: f4 stride 121 (odd) -> conflict-free
constexpr float INV_EXT = 1.0f / 0.6f;

typedef unsigned long long u64;

// ---- device-global scratch ----
__device__ float g_wf[NQ * A * KC];      // stage-1 output, [na][kc]

// ---- packed f32x2 helpers (bit-identical to scalar fp32 FMA) ----
__device__ __forceinline__ void fma2(u64& acc, u64 a, u64 b) {
    asm("fma.rn.f32x2 %0, %1, %2, %0;" : "+l"(acc) : "l"(a), "l"(b));
}
__device__ __forceinline__ u64 dup2(float x) {
    u64 r; asm("mov.b64 %0, {%1, %1};" : "=l"(r) : "f"(x)); return r;
}
__device__ __forceinline__ float lo32(u64 v) {
    float a, b; asm("mov.b64 {%0, %1}, %2;" : "=f"(a), "=f"(b) : "l"(v)); return a;
}
__device__ __forceinline__ float hi32(u64 v) {
    float a, b; asm("mov.b64 {%0, %1}, %2;" : "=f"(a), "=f"(b) : "l"(v)); return b;
}
__device__ __forceinline__ u64 pack2(float lo, float hi) {
    u64 r; asm("mov.b64 %0, {%1, %2};" : "=l"(r) : "f"(lo), "f"(hi)); return r;
}
__device__ __forceinline__ unsigned s2u(const void* p) {
    unsigned r;
    asm("{ .reg .u64 t; cvta.to.shared.u64 t, %1; cvt.u32.u64 %0, t; }"
        : "=r"(r) : "l"(p));
    return r;
}

// =====================  Kernel 1 (FIRST launch): stages 0+1  =====================
// 256 threads = 8 warps; warp w owns query blockIdx.x*8+w.
// Single b-loop over ALL 4 anchors: lane = (anchor = lane>>3, c4 = (lane&7)*4).
// Manual unroll-4 b-loop: 4 front-batched LDG.128 (MLP=4) per group.
constexpr int S1_W2F   = QB * NB * 68;
constexpr int S1_SMEMB = S1_W2F * 4 + 64 * 16 + QB * 32 * 4;

__global__ __launch_bounds__(256, 2) void stage1_kernel(
    const float* __restrict__ q_pts,
    const float* __restrict__ s_pts,
    const int*   __restrict__ nbr,
    const float* __restrict__ x,
    const float* __restrict__ kp,
    const float* __restrict__ anchors)
{
    extern __shared__ float sm[];
    float*  s_w2   = sm;                           // [8 warps][32 b][68]
    float4* s_kp   = (float4*)(sm + S1_W2F);       // [A*16]
    int*    s_addr = (int*)(sm + S1_W2F + 64 * 4); // [8 warps][32 b]

    const int tid  = threadIdx.x;
    const int w    = tid >> 5;
    const int lane = tid & 31;
    const int q    = blockIdx.x * QB + w;

    if (tid < A * K) {
        int a = tid / K;
        int k = tid - a * K;
        float p0 = kp[k * 3 + 0], p1 = kp[k * 3 + 1], p2 = kp[k * 3 + 2];
        const float* R = anchors + a * 9;
        float r0 = R[0] * p0 + R[1] * p1 + R[2] * p2;
        float r1 = R[3] * p0 + R[4] * p1 + R[5] * p2;
        float r2 = R[6] * p0 + R[7] * p1 + R[8] * p2;
        s_kp[a * 16 + k] = make_float4(r0, r1, r2, r0 * r0 + r1 * r1 + r2 * r2);
    }

    // stage 0: gather + center (lane = neighbor b)
    int m = nbr[q * NB + lane];
    s_addr[w * 32 + lane] = m * 32;     // float4 units
    float dx = s_pts[m * 3 + 0] - q_pts[q * 3 + 0];
    float dy = s_pts[m * 3 + 1] - q_pts[q * 3 + 1];
    float dz = s_pts[m * 3 + 2] - q_pts[q * 3 + 2];
    float n2 = dx * dx + dy * dy + dz * dz;
    __syncthreads();

    // phase A: influence weights for ALL anchors (lane = b)
    float* swq = s_w2 + w * (NB * 68);
    #pragma unroll
    for (int a = 0; a < A; a++) {
        float wk[16];
        #pragma unroll
        for (int k = 0; k < K; k++) {
            float4 g = s_kp[a * 16 + k];
            float cross = dx * g.x + dy * g.y + dz * g.z;
            float sq = fmaxf(fmaf(-2.0f, cross, n2 + g.w), 1e-12f);
            wk[k] = fmaxf(1.0f - sqrtf(sq) * INV_EXT, 0.0f);
        }
        wk[15] = 0.0f;
        float4* dst = (float4*)(swq + lane * 68 + a * 16);
        dst[0] = make_float4(wk[0],  wk[1],  wk[2],  wk[3]);
        dst[1] = make_float4(wk[4],  wk[5],  wk[6],  wk[7]);
        dst[2] = make_float4(wk[8],  wk[9],  wk[10], wk[11]);
        dst[3] = make_float4(wk[12], wk[13], wk[14], wk[15]);
    }
    __syncwarp();

    // phase B: single b-loop, lane's anchor slice; 4 LDGs batched up front.
    u64 acc[4][8];
    #pragma unroll
    for (int c = 0; c < 4; c++)
        #pragma unroll
        for (int j = 0; j < 8; j++) acc[c][j] = 0ULL;

    const float4* xrow   = (const float4*)x;
    const int*    myaddr = s_addr + w * 32;
    const float*  wkbase = swq + (lane >> 3) * 16;

#define S1_PROC(XQ, BB)                                                        \
    {                                                                          \
        const ulonglong2* wp_ = (const ulonglong2*)(wkbase + (BB) * 68);       \
        ulonglong2 k01 = wp_[0], k23 = wp_[1], k45 = wp_[2], k67 = wp_[3];     \
        u64 d0 = dup2((XQ).x), d1 = dup2((XQ).y),                              \
            d2 = dup2((XQ).z), d3 = dup2((XQ).w);                              \
        fma2(acc[0][0], k01.x, d0); fma2(acc[0][1], k01.y, d0);                \
        fma2(acc[0][2], k23.x, d0); fma2(acc[0][3], k23.y, d0);                \
        fma2(acc[0][4], k45.x, d0); fma2(acc[0][5], k45.y, d0);                \
        fma2(acc[0][6], k67.x, d0); fma2(acc[0][7], k67.y, d0);                \
        fma2(acc[1][0], k01.x, d1); fma2(acc[1][1], k01.y, d1);                \
        fma2(acc[1][2], k23.x, d1); fma2(acc[1][3], k23.y, d1);                \
        fma2(acc[1][4], k45.x, d1); fma2(acc[1][5], k45.y, d1);                \
        fma2(acc[1][6], k67.x, d1); fma2(acc[1][7], k67.y, d1);                \
        fma2(acc[2][0], k01.x, d2); fma2(acc[2][1], k01.y, d2);                \
        fma2(acc[2][2], k23.x, d2); fma2(acc[2][3], k23.y, d2);                \
        fma2(acc[2][4], k45.x, d2); fma2(acc[2][5], k45.y, d2);                \
        fma2(acc[2][6], k67.x, d2); fma2(acc[2][7], k67.y, d2);                \
        fma2(acc[3][0], k01.x, d3); fma2(acc[3][1], k01.y, d3);                \
        fma2(acc[3][2], k23.x, d3); fma2(acc[3][3], k23.y, d3);                \
        fma2(acc[3][4], k45.x, d3); fma2(acc[3][5], k45.y, d3);                \
        fma2(acc[3][6], k67.x, d3); fma2(acc[3][7], k67.y, d3);                \
    }

    #pragma unroll 2
    for (int b0 = 0; b0 < NB; b0 += 4) {
        // front-batched gathers: MLP = 4
        float4 x0 = __ldg(xrow + myaddr[b0 + 0] + lane);
        float4 x1 = __ldg(xrow + myaddr[b0 + 1] + lane);
        float4 x2 = __ldg(xrow + myaddr[b0 + 2] + lane);
        float4 x3 = __ldg(xrow + myaddr[b0 + 3] + lane);
        S1_PROC(x0, b0 + 0)
        S1_PROC(x1, b0 + 1)
        S1_PROC(x2, b0 + 2)
        S1_PROC(x3, b0 + 3)
    }
#undef S1_PROC

    // store wf: lane's anchor row, 4 channels, 15 k's
    {
        const int a  = lane >> 3;
        const int c4 = (lane & 7) * 4;
        float* dst = g_wf + ((long)(q * A + a)) * KC + c4;
        #pragma unroll
        for (int j = 0; j < 8; j++) {
            *(float4*)(dst + (2 * j) * CIN) =
                make_float4(lo32(acc[0][j]), lo32(acc[1][j]),
                            lo32(acc[2][j]), lo32(acc[3][j]));
            if (j < 7) {
                *(float4*)(dst + (2 * j + 1) * CIN) =
                    make_float4(hi32(acc[0][j]), hi32(acc[1][j]),
                                hi32(acc[2][j]), hi32(acc[3][j]));
            }
        }
    }
}

// =====================  Kernel 2: persistent stage-2 GEMM  =====================
// [64000 x 480] @ [480 x 32]. 152 blocks x 512 threads, 1/SM (occ 1).
// Per pass: TWO 32-row tiles. 16 warps = 4 col-groups (8 cols) x 4 kc-quarters
// (120 kc). Per 4-kc iter: 2 per-lane f LDS.128 + 8 broadcast weight LDS.128
// for 32 FFMA2 -> crossbar ~ FFMA parity. Weights packed into smem once.
constexpr int S2_WU    = (KC / 2) * COUT;         // 7680 packed u64 weights
constexpr int S2_TILEF = 32 * WF_PADF;            // 15488 floats per tile
constexpr int S2_PARTF4 = 4 * 2 * 32 * 9;         // partials [h][t][row][9]
constexpr int S2_SMEMB = S2_WU * 8 + 2 * S2_TILEF * 4 + S2_PARTF4 * 16; // 222208

__global__ __launch_bounds__(512, 1) void stage2_kernel(
    const float* __restrict__ weights, float* __restrict__ out)
{
    extern __shared__ float sm2[];
    u64*    sw   = (u64*)sm2;                                   // [7680]
    float*  st   = sm2 + S2_WU * 2;                             // [2][32][484]
    float4* part = (float4*)(sm2 + S2_WU * 2 + 2 * S2_TILEF);   // [4][2][32][9]

    const int tid  = threadIdx.x;
    const int w    = tid >> 5;
    const int lane = tid & 31;
    const int g    = w & 3;        // col-group: cols 8g..8g+7
    const int h    = w >> 2;       // kc quarter: kc [120h, 120h+120)
    const int dc   = g * 8;

    // pack weights into smem once: sw[p*32+d] = (W[2p][d], W[2p+1][d])
    for (int i = tid; i < S2_WU; i += 512) {
        int p = i >> 5;
        int d = i & 31;
        sw[i] = pack2(__ldg(weights + (2 * p) * COUT + d),
                      __ldg(weights + (2 * p + 1) * COUT + d));
    }
    __syncthreads();

    const u64* wpB = sw + (h * 60) * COUT;   // this quarter's pair rows

    for (int p = blockIdx.x; p < NPAIR; p += gridDim.x) {
        // synchronous pair load: 64 rows x 120 f4 = 7680 f4, 15 per thread
        {
            const float4* src = (const float4*)(g_wf + (long)p * 64 * KC);
            #pragma unroll
            for (int j = 0; j < 15; j++) {
                int i    = tid + j * 512;
                int r64  = i / 120;
                int c4   = i - r64 * 120;
                int t    = r64 >> 5;
                int r    = r64 & 31;
                asm volatile("cp.async.ca.shared.global [%0], [%1], 16;"
                             :: "r"(s2u(st + t * S2_TILEF + r * WF_PADF + c4 * 4)),
                                "l"(src + i) : "memory");
            }
            asm volatile("cp.async.commit_group;" ::: "memory");
            asm volatile("cp.async.wait_group 0;" ::: "memory");
            __syncthreads();
        }

        const float* fw0 = st + lane * WF_PADF + h * 120;
        const float* fw1 = fw0 + S2_TILEF;

        u64 acc0[8], acc1[8];   // per tile, per col (even+odd merged)
        #pragma unroll
        for (int c = 0; c < 8; c++) { acc0[c] = 0ULL; acc1[c] = 0ULL; }

        #pragma unroll 2
        for (int kq = 0; kq < 30; kq++) {
            ulonglong2 f0 = *(const ulonglong2*)(fw0 + kq * 4);
            ulonglong2 f1 = *(const ulonglong2*)(fw1 + kq * 4);
            const u64* wep = wpB + (2 * kq) * COUT + dc;        // even pair
            const u64* wop = wep + COUT;                        // odd pair
            ulonglong2 we0 = *(const ulonglong2*)(wep);
            ulonglong2 we1 = *(const ulonglong2*)(wep + 2);
            ulonglong2 we2 = *(const ulonglong2*)(wep + 4);
            ulonglong2 we3 = *(const ulonglong2*)(wep + 6);
            fma2(acc0[0], f0.x, we0.x); fma2(acc0[1], f0.x, we0.y);
            fma2(acc0[2], f0.x, we1.x); fma2(acc0[3], f0.x, we1.y);
            fma2(acc0[4], f0.x, we2.x); fma2(acc0[5], f0.x, we2.y);
            fma2(acc0[6], f0.x, we3.x); fma2(acc0[7], f0.x, we3.y);
            fma2(acc1[0], f1.x, we0.x); fma2(acc1[1], f1.x, we0.y);
            fma2(acc1[2], f1.x, we1.x); fma2(acc1[3], f1.x, we1.y);
            fma2(acc1[4], f1.x, we2.x); fma2(acc1[5], f1.x, we2.y);
            fma2(acc1[6], f1.x, we3.x); fma2(acc1[7], f1.x, we3.y);
            ulonglong2 wo0 = *(const ulonglong2*)(wop);
            ulonglong2 wo1 = *(const ulonglong2*)(wop + 2);
            ulonglong2 wo2 = *(const ulonglong2*)(wop + 4);
            ulonglong2 wo3 = *(const ulonglong2*)(wop + 6);
            fma2(acc0[0], f0.y, wo0.x); fma2(acc0[1], f0.y, wo0.y);
            fma2(acc0[2], f0.y, wo1.x); fma2(acc0[3], f0.y, wo1.y);
            fma2(acc0[4], f0.y, wo2.x); fma2(acc0[5], f0.y, wo2.y);
            fma2(acc0[6], f0.y, wo3.x); fma2(acc0[7], f0.y, wo3.y);
            fma2(acc1[0], f1.y, wo0.x); fma2(acc1[1], f1.y, wo0.y);
            fma2(acc1[2], f1.y, wo1.x); fma2(acc1[3], f1.y, wo1.y);
            fma2(acc1[4], f1.y, wo2.x); fma2(acc1[5], f1.y, wo2.y);
            fma2(acc1[6], f1.y, wo3.x); fma2(acc1[7], f1.y, wo3.y);
        }

        // partials: [h][t][row][g*2 + half]
        part[((h * 2 + 0) * 32 + lane) * 9 + g * 2 + 0] =
            make_float4(lo32(acc0[0]) + hi32(acc0[0]), lo32(acc0[1]) + hi32(acc0[1]),
                        lo32(acc0[2]) + hi32(acc0[2]), lo32(acc0[3]) + hi32(acc0[3]));
        part[((h * 2 + 0) * 32 + lane) * 9 + g * 2 + 1] =
            make_float4(lo32(acc0[4]) + hi32(acc0[4]), lo32(acc0[5]) + hi32(acc0[5]),
                        lo32(acc0[6]) + hi32(acc0[6]), lo32(acc0[7]) + hi32(acc0[7]));
        part[((h * 2 + 1) * 32 + lane) * 9 + g * 2 + 0] =
            make_float4(lo32(acc1[0]) + hi32(acc1[0]), lo32(acc1[1]) + hi32(acc1[1]),
                        lo32(acc1[2]) + hi32(acc1[2]), lo32(acc1[3]) + hi32(acc1[3]));
        part[((h * 2 + 1) * 32 + lane) * 9 + g * 2 + 1] =
            make_float4(lo32(acc1[4]) + hi32(acc1[4]), lo32(acc1[5]) + hi32(acc1[5]),
                        lo32(acc1[6]) + hi32(acc1[6]), lo32(acc1[7]) + hi32(acc1[7]));
        __syncthreads();

        // reduce 4 quarters + store: tid -> (t, row, q4)
        {
            int t   = tid >> 8;
            int row = (tid >> 3) & 31;
            int q4  = tid & 7;
            float4 v0 = part[((0 * 2 + t) * 32 + row) * 9 + q4];
            float4 v1 = part[((1 * 2 + t) * 32 + row) * 9 + q4];
            float4 v2 = part[((2 * 2 + t) * 32 + row) * 9 + q4];
            float4 v3 = part[((3 * 2 + t) * 32 + row) * 9 + q4];
            float4 v = make_float4((v0.x + v1.x) + (v2.x + v3.x),
                                   (v0.y + v1.y) + (v2.y + v3.y),
                                   (v0.z + v1.z) + (v2.z + v3.z),
                                   (v0.w + v1.w) + (v2.w + v3.w));
            long grow = (long)p * 64 + t * 32 + row;
            *(float4*)(out + grow * COUT + q4 * 4) = v;
        }
        // next pass's cp.async (writes st) is ordered after this pass's st reads
        // by the part-write __syncthreads above; part overwrite is ordered by the
        // next pass's post-wait __syncthreads.
    }
}

extern "C" void kernel_launch(void* const* d_in, const int* in_sizes, int n_in,
                              void* d_out, int out_size) {
    const float* q_pts   = (const float*)d_in[0];
    const float* s_pts   = (const float*)d_in[1];
    const int*   nbr     = (const int*)  d_in[2];
    const float* x       = (const float*)d_in[3];
    const float* kp      = (const float*)d_in[4];
    const float* anchors = (const float*)d_in[5];
    const float* weights = (const float*)d_in[6];
    float* out = (float*)d_out;

    const int Nq = in_sizes[2] / NB;   // 16000

    static bool attr_set = false;
    if (!attr_set) {
        cudaFuncSetAttribute(stage1_kernel,
                             cudaFuncAttributeMaxDynamicSharedMemorySize, S1_SMEMB);
        cudaFuncSetAttribute(stage2_kernel,
                             cudaFuncAttributeMaxDynamicSharedMemorySize, S2_SMEMB);
        attr_set = true;
    }

    // stage1 first so the ncu capture slot profiles it
    stage1_kernel<<<Nq / QB, 256, S1_SMEMB>>>(q_pts, s_pts, nbr, x, kp, anchors);
    stage2_kernel<<<152, 512, S2_SMEMB>>>(weights, out);
}